// round 2
// baseline (speedup 1.0000x reference)
#include <cuda_runtime.h>
#include <math.h>

typedef unsigned long long ull;

namespace {
constexpr int kB = 2, kC = 20000, kH = 64, kM = 8, kE = 200000, kP = 3;
constexpr int kNR = kB * kE;      // 400000 message rows
constexpr int kNC = kB * kC;      // 40000 node rows
constexpr int kIn1 = 2 * kH + 4;  // 132
constexpr int TILE = 128;
constexpr int TB = 512;

// msg_kernel shared layout (float offsets)
constexpr int OFF_W1 = 0;           // 132*64 = 8448
constexpr int OFF_W2 = 8448;        // 4096
constexpr int OFF_P1 = 12544;       // 4096
constexpr int OFF_P2 = 16640;       // 64
constexpr int OFF_B1 = 16704;       // 64
constexpr int OFF_B2 = 16768;       // 64
constexpr int OFF_PB1 = 16832;      // 64
constexpr int OFF_X = 16896;        // 128*132 = 16896 (aliased as Msg later)
constexpr int OFF_H = 33792;        // 128*68  = 8704
constexpr int OFF_REL = 42496;      // 128*3
constexpr int OFF_WT = 42880;       // 128
constexpr int OFF_DST = 43008;      // 128 (int)
constexpr int MSG_SMEM_FLOATS = 43136;

// node_kernel shared layout
constexpr int NOFF_U1 = 0;          // 128*64 = 8192
constexpr int NOFF_U2 = 8192;       // 4096
constexpr int NOFF_UB1 = 12288;     // 64
constexpr int NOFF_UB2 = 12352;     // 64
constexpr int NOFF_X = 12416;       // 128*132 = 16896
constexpr int NOFF_H = 29312;       // 128*68  = 8704
constexpr int NODE_SMEM_FLOATS = 38016;
}  // namespace

// Scratch (static device globals: no runtime allocation)
__device__ float g_agg[kNC * kH];
__device__ float g_posupd[kNC * kP];
__device__ float g_inv[kNR * 4];
__device__ float g_npos[kNC * kM * 3];
__device__ float g_np2[kNC * kM];
__device__ float g_cent[kNC * 3];
__device__ unsigned g_mbits[kC];

// ---- packed f32x2 helpers (sm_100+ FFMA2, PTX-only path) ----
__device__ __forceinline__ ull dup2(float v) {
  ull r;
  asm("mov.b64 %0, {%1, %1};" : "=l"(r) : "f"(v));
  return r;
}
__device__ __forceinline__ void ffma2(ull& d, ull a, ull b) {
  asm("fma.rn.f32x2 %0, %1, %2, %0;" : "+l"(d) : "l"(a), "l"(b));
}
__device__ __forceinline__ float2 unpack2(ull v) {
  float2 f;
  asm("mov.b64 {%0, %1}, %2;" : "=f"(f.x), "=f"(f.y) : "l"(v));
  return f;
}

__device__ __forceinline__ float silu_f(float v) {
  return __fdividef(v, 1.f + __expf(-v));
}

// 4-row x 4-col (2 f32x2 pairs) register tile over K, x rows in smem
// (stride XS, multiple of 4), W row-major [K,64] in smem, bias[64] in smem.
template <int K, int XS>
__device__ __forceinline__ void gemm_tile_f32x2(
    const float* __restrict__ xbase, int row0, const float* __restrict__ W,
    int cg, const float* __restrict__ bias, ull acc[4][2]) {
  const float* x0 = xbase + (row0 + 0) * XS;
  const float* x1 = xbase + (row0 + 1) * XS;
  const float* x2 = xbase + (row0 + 2) * XS;
  const float* x3 = xbase + (row0 + 3) * XS;
#pragma unroll
  for (int i = 0; i < 4; i++) {
    acc[i][0] = *(const ull*)(bias + cg * 4 + 0);
    acc[i][1] = *(const ull*)(bias + cg * 4 + 2);
  }
#pragma unroll 2
  for (int k = 0; k < K; k += 4) {
    float4 xv0 = *(const float4*)(x0 + k);
    float4 xv1 = *(const float4*)(x1 + k);
    float4 xv2 = *(const float4*)(x2 + k);
    float4 xv3 = *(const float4*)(x3 + k);
#pragma unroll
    for (int kk = 0; kk < 4; kk++) {
      ulonglong2 w = *(const ulonglong2*)(W + (k + kk) * 64 + cg * 4);
      ull d0 = dup2(((const float*)&xv0)[kk]);
      ull d1 = dup2(((const float*)&xv1)[kk]);
      ull d2 = dup2(((const float*)&xv2)[kk]);
      ull d3 = dup2(((const float*)&xv3)[kk]);
      ffma2(acc[0][0], d0, w.x);
      ffma2(acc[0][1], d0, w.y);
      ffma2(acc[1][0], d1, w.x);
      ffma2(acc[1][1], d1, w.y);
      ffma2(acc[2][0], d2, w.x);
      ffma2(acc[2][1], d2, w.y);
      ffma2(acc[3][0], d3, w.x);
      ffma2(acc[3][1], d3, w.y);
    }
  }
}

__global__ void zero_kernel() {
  int i = blockIdx.x * blockDim.x + threadIdx.x;
  if (i < kNC * kH) g_agg[i] = 0.f;
  if (i < kNC * kP) g_posupd[i] = 0.f;
}

__global__ void prep_kernel(const float* __restrict__ positions,
                            const int* __restrict__ cni,
                            const float* __restrict__ mask) {
  int i = blockIdx.x * blockDim.x + threadIdx.x;
  if (i >= kNC) return;
  int b = i / kC, c = i - b * kC;
  float sx = 0.f, sy = 0.f, sz = 0.f, cnt = 0.f;
  unsigned bits = 0;
#pragma unroll
  for (int m = 0; m < kM; m++) {
    int idx = cni[c * kM + m];
    const float* p = positions + ((size_t)b * kC + idx) * kP;
    float x = p[0], y = p[1], z = p[2];
    g_npos[((size_t)i * kM + m) * 3 + 0] = x;
    g_npos[((size_t)i * kM + m) * 3 + 1] = y;
    g_npos[((size_t)i * kM + m) * 3 + 2] = z;
    g_np2[i * kM + m] = x * x + y * y + z * z;
    float mk = mask[c * kM + m];
    if (mk > 0.f) { bits |= (1u << m); sx += x; sy += y; sz += z; cnt += 1.f; }
  }
  float den = fmaxf(cnt, 1e-12f);
  g_cent[i * 3 + 0] = sx / den;
  g_cent[i * 3 + 1] = sy / den;
  g_cent[i * 3 + 2] = sz / den;
  if (b == 0) g_mbits[c] = bits;
}

__global__ void __launch_bounds__(256) inv_kernel(
    const float* __restrict__ positions, const int* __restrict__ ei) {
  int g = blockIdx.x * blockDim.x + threadIdx.x;
  if (g >= kNR) return;
  int b = g / kE, e = g - b * kE;
  int src = ei[e], dst = ei[kE + e];
  int is = b * kC + src, id = b * kC + dst;

  float sp[24], dp[24], sp2[8], dp2[8];
  {
    const float4* a = (const float4*)(g_npos + (size_t)is * 24);
    float4* o = (float4*)sp;
#pragma unroll
    for (int q = 0; q < 6; q++) o[q] = a[q];
    const float4* a2 = (const float4*)(g_npos + (size_t)id * 24);
    float4* o2 = (float4*)dp;
#pragma unroll
    for (int q = 0; q < 6; q++) o2[q] = a2[q];
    const float4* s2 = (const float4*)(g_np2 + (size_t)is * 8);
    ((float4*)sp2)[0] = s2[0]; ((float4*)sp2)[1] = s2[1];
    const float4* d2 = (const float4*)(g_np2 + (size_t)id * 8);
    ((float4*)dp2)[0] = d2[0]; ((float4*)dp2)[1] = d2[1];
  }
  unsigned mx = g_mbits[src], my = g_mbits[dst];
  float pairwise = 0.f, hxy = 0.f;
  float colmin[8];
#pragma unroll
  for (int n = 0; n < 8; n++) colmin[n] = 3.4e38f;
#pragma unroll
  for (int m = 0; m < 8; m++) {
    if ((mx >> m) & 1) {
      float rowmin = 3.4e38f;
      float ax = sp[m * 3], ay = sp[m * 3 + 1], az = sp[m * 3 + 2], a2 = sp2[m];
#pragma unroll
      for (int n = 0; n < 8; n++) {
        if ((my >> n) & 1) {
          float s = a2 + dp2[n] -
                    2.f * (ax * dp[n * 3] + ay * dp[n * 3 + 1] + az * dp[n * 3 + 2]);
          float d = sqrtf(fmaxf(s, 0.f) + 1e-12f);
          pairwise += d;
          rowmin = fminf(rowmin, d);
          colmin[n] = fminf(colmin[n], d);
        }
      }
      hxy = fmaxf(hxy, rowmin);
    }
  }
  float hyx = 0.f;
#pragma unroll
  for (int n = 0; n < 8; n++)
    if ((my >> n) & 1) hyx = fmaxf(hyx, colmin[n]);
  float haus = fmaxf(hxy, hyx);

  float c0 = g_cent[is * 3 + 0] - g_cent[id * 3 + 0];
  float c1 = g_cent[is * 3 + 1] - g_cent[id * 3 + 1];
  float c2 = g_cent[is * 3 + 2] - g_cent[id * 3 + 2];
  float centroid = sqrtf(c0 * c0 + c1 * c1 + c2 * c2);

  const float* ps = positions + (size_t)is * kP;
  const float* pd = positions + (size_t)id * kP;
  float r0 = ps[0] - pd[0], r1 = ps[1] - pd[1], r2 = ps[2] - pd[2];
  float dist = sqrtf(r0 * r0 + r1 * r1 + r2 * r2);

  ((float4*)g_inv)[g] = make_float4(dist, pairwise, centroid, haus);
}

__global__ void __launch_bounds__(TB) msg_kernel(
    const float* __restrict__ features, const float* __restrict__ positions,
    const int* __restrict__ ei,
    const float* __restrict__ W1, const float* __restrict__ b1,
    const float* __restrict__ W2, const float* __restrict__ b2,
    const float* __restrict__ P1, const float* __restrict__ pb1,
    const float* __restrict__ P2, const float* __restrict__ pb2) {
  extern __shared__ float sm[];
  float* sW1 = sm + OFF_W1;
  float* sW2 = sm + OFF_W2;
  float* sP1 = sm + OFF_P1;
  float* sP2 = sm + OFF_P2;
  float* sb1 = sm + OFF_B1;
  float* sb2 = sm + OFF_B2;
  float* spb1 = sm + OFF_PB1;
  float* sX = sm + OFF_X;   // [128][132]; cols 0..63 aliased as Msg after GEMM2
  float* sH = sm + OFF_H;   // [128][68]
  float* sRel = sm + OFF_REL;
  float* sWt = sm + OFF_WT;
  int* sDst = (int*)(sm + OFF_DST);

  int tid = threadIdx.x;
  for (int i = tid; i < kIn1 * 64; i += TB) sW1[i] = W1[i];
  for (int i = tid; i < 64 * 64; i += TB) { sW2[i] = W2[i]; sP1[i] = P1[i]; }
  if (tid < 64) { sP2[tid] = P2[tid]; sb1[tid] = b1[tid]; sb2[tid] = b2[tid]; spb1[tid] = pb1[tid]; }
  float pb2v = pb2[0];

  // ---- gather: 4 threads per row ----
  int lr = tid >> 2, ts = tid & 3;
  int gr = blockIdx.x * TILE + lr;
  if (gr < kNR) {
    int b = gr / kE, e = gr - b * kE;
    int src = ei[e], dst = ei[kE + e];
    int is = b * kC + src, id = b * kC + dst;
    const float4* fs = (const float4*)(features + (size_t)is * kH);
    const float4* fd = (const float4*)(features + (size_t)id * kH);
    float4* xr = (float4*)(sX + lr * 132);
#pragma unroll
    for (int q = 0; q < 4; q++) xr[ts * 4 + q] = fs[ts * 4 + q];
#pragma unroll
    for (int q = 0; q < 4; q++) xr[16 + ts * 4 + q] = fd[ts * 4 + q];
    if (ts == 0) {
      float4 iv = ((const float4*)g_inv)[gr];
      sX[lr * 132 + 128] = iv.x;
      sX[lr * 132 + 129] = iv.y;
      sX[lr * 132 + 130] = iv.z;
      sX[lr * 132 + 131] = iv.w;
      sDst[lr] = id;
      const float* ps = positions + (size_t)is * kP;
      const float* pd = positions + (size_t)id * kP;
      sRel[lr * 3 + 0] = ps[0] - pd[0];
      sRel[lr * 3 + 1] = ps[1] - pd[1];
      sRel[lr * 3 + 2] = ps[2] - pd[2];
    }
  } else if (ts == 0) {
    sDst[lr] = -1;
  }
  __syncthreads();

  int rg = tid >> 4, cg = tid & 15;  // rg 0..31 (4 rows each), cg 0..15 (4 cols)
  int row0 = rg * 4;
  ull acc[4][2];

  // ---- GEMM1: silu(X[128,132] @ W1 + b1) -> sH ----
  gemm_tile_f32x2<kIn1, 132>(sX, row0, sW1, cg, sb1, acc);
#pragma unroll
  for (int i = 0; i < 4; i++)
#pragma unroll
    for (int p = 0; p < 2; p++) {
      float2 h = unpack2(acc[i][p]);
      h.x = silu_f(h.x);
      h.y = silu_f(h.y);
      *(float2*)(sH + (row0 + i) * 68 + cg * 4 + 2 * p) = h;
    }
  __syncthreads();

  // ---- GEMM2: H @ W2 + b2 -> Msg (into sX cols 0..63; sX free now) ----
  gemm_tile_f32x2<64, 68>(sH, row0, sW2, cg, sb2, acc);
#pragma unroll
  for (int i = 0; i < 4; i++)
#pragma unroll
    for (int p = 0; p < 2; p++) {
      float2 v = unpack2(acc[i][p]);
      *(float2*)(sX + (row0 + i) * 132 + cg * 4 + 2 * p) = v;
    }
  __syncthreads();

  // ---- GEMM3: silu(Msg @ P1 + pb1) . P2, tanh -> wt ----
  gemm_tile_f32x2<64, 132>(sX, row0, sP1, cg, spb1, acc);
  float part[4] = {0.f, 0.f, 0.f, 0.f};
#pragma unroll
  for (int i = 0; i < 4; i++)
#pragma unroll
    for (int p = 0; p < 2; p++) {
      float2 h = unpack2(acc[i][p]);
      part[i] = fmaf(silu_f(h.x), sP2[cg * 4 + 2 * p], part[i]);
      part[i] = fmaf(silu_f(h.y), sP2[cg * 4 + 2 * p + 1], part[i]);
    }
#pragma unroll
  for (int i = 0; i < 4; i++) {
    float v = part[i];
    v += __shfl_xor_sync(0xffffffffu, v, 1);
    v += __shfl_xor_sync(0xffffffffu, v, 2);
    v += __shfl_xor_sync(0xffffffffu, v, 4);
    v += __shfl_xor_sync(0xffffffffu, v, 8);
    if (cg == 0) sWt[row0 + i] = tanhf(v + pb2v);
  }
  __syncthreads();

  // ---- scatter: messages -> agg, wt*rel -> pos_upd ----
  int ob = sDst[lr];
  if (ob >= 0) {
    float* ap = g_agg + (size_t)ob * kH;
    const float* mp = sX + lr * 132;
#pragma unroll
    for (int q = 0; q < 16; q++) atomicAdd(ap + ts * 16 + q, mp[ts * 16 + q]);
    if (ts == 0) {
      float w = sWt[lr];
      float* pp = g_posupd + (size_t)ob * kP;
      atomicAdd(pp + 0, w * sRel[lr * 3 + 0]);
      atomicAdd(pp + 1, w * sRel[lr * 3 + 1]);
      atomicAdd(pp + 2, w * sRel[lr * 3 + 2]);
    }
  }
}

__global__ void __launch_bounds__(TB) node_kernel(
    const float* __restrict__ features, const float* __restrict__ degree,
    const float* __restrict__ U1, const float* __restrict__ ub1,
    const float* __restrict__ U2, const float* __restrict__ ub2,
    float* __restrict__ out_feat) {
  extern __shared__ float sm[];
  float* sU1 = sm + NOFF_U1;
  float* sU2 = sm + NOFF_U2;
  float* sub1 = sm + NOFF_UB1;
  float* sub2 = sm + NOFF_UB2;
  float* sX = sm + NOFF_X;  // [128][132] (128 cols used)
  float* sH = sm + NOFF_H;  // [128][68]

  int tid = threadIdx.x;
  for (int i = tid; i < 128 * 64; i += TB) sU1[i] = U1[i];
  for (int i = tid; i < 64 * 64; i += TB) sU2[i] = U2[i];
  if (tid < 64) { sub1[tid] = ub1[tid]; sub2[tid] = ub2[tid]; }

  int lr = tid >> 2, ts = tid & 3;
  int gr = blockIdx.x * TILE + lr;
  if (gr < kNC) {
    int c = gr % kC;
    float invd = 1.f / fmaxf(degree[c], 1.f);
    const float4* fp = (const float4*)(features + (size_t)gr * kH);
    const float4* ap = (const float4*)(g_agg + (size_t)gr * kH);
    float4* xr = (float4*)(sX + lr * 132);
#pragma unroll
    for (int q = 0; q < 4; q++) xr[ts * 4 + q] = fp[ts * 4 + q];
#pragma unroll
    for (int q = 0; q < 4; q++) {
      float4 a = ap[ts * 4 + q];
      a.x *= invd; a.y *= invd; a.z *= invd; a.w *= invd;
      xr[16 + ts * 4 + q] = a;
    }
  }
  __syncthreads();

  int rg = tid >> 4, cg = tid & 15;
  int row0 = rg * 4;
  ull acc[4][2];

  gemm_tile_f32x2<128, 132>(sX, row0, sU1, cg, sub1, acc);
#pragma unroll
  for (int i = 0; i < 4; i++)
#pragma unroll
    for (int p = 0; p < 2; p++) {
      float2 h = unpack2(acc[i][p]);
      h.x = silu_f(h.x);
      h.y = silu_f(h.y);
      *(float2*)(sH + (row0 + i) * 68 + cg * 4 + 2 * p) = h;
    }
  __syncthreads();

  gemm_tile_f32x2<64, 68>(sH, row0, sU2, cg, sub2, acc);
#pragma unroll
  for (int i = 0; i < 4; i++) {
    int r = row0 + i;
    int g2 = blockIdx.x * TILE + r;
    if (g2 < kNC) {
      float2 v0 = unpack2(acc[i][0]);
      float2 v1 = unpack2(acc[i][1]);
      float4 o;
      o.x = sX[r * 132 + cg * 4 + 0] + v0.x;
      o.y = sX[r * 132 + cg * 4 + 1] + v0.y;
      o.z = sX[r * 132 + cg * 4 + 2] + v1.x;
      o.w = sX[r * 132 + cg * 4 + 3] + v1.y;
      ((float4*)(out_feat + (size_t)g2 * kH))[cg] = o;
    }
  }
}

__global__ void pos_kernel(const float* __restrict__ positions,
                           float* __restrict__ out_pos) {
  int i = blockIdx.x * blockDim.x + threadIdx.x;
  if (i < kNC * kP) out_pos[i] = positions[i] + g_posupd[i];
}

extern "C" void kernel_launch(void* const* d_in, const int* in_sizes, int n_in,
                              void* d_out, int out_size) {
  const float* features = (const float*)d_in[0];
  const float* positions = (const float*)d_in[1];
  const int* edge_index = (const int*)d_in[2];
  const float* degree = (const float*)d_in[3];
  const int* cni = (const int*)d_in[4];
  const float* mask = (const float*)d_in[5];
  const float* W1 = (const float*)d_in[6];
  const float* b1 = (const float*)d_in[7];
  const float* W2 = (const float*)d_in[8];
  const float* b2 = (const float*)d_in[9];
  const float* P1 = (const float*)d_in[10];
  const float* pb1 = (const float*)d_in[11];
  const float* P2 = (const float*)d_in[12];
  const float* pb2 = (const float*)d_in[13];
  const float* U1 = (const float*)d_in[14];
  const float* ub1 = (const float*)d_in[15];
  const float* U2 = (const float*)d_in[16];
  const float* ub2 = (const float*)d_in[17];

  float* out_feat = (float*)d_out;
  float* out_pos = out_feat + (size_t)kNC * kH;

  size_t msg_smem = (size_t)MSG_SMEM_FLOATS * sizeof(float);    // 172,544 B
  size_t node_smem = (size_t)NODE_SMEM_FLOATS * sizeof(float);  // 152,064 B
  cudaFuncSetAttribute(msg_kernel, cudaFuncAttributeMaxDynamicSharedMemorySize,
                       (int)msg_smem);
  cudaFuncSetAttribute(node_kernel, cudaFuncAttributeMaxDynamicSharedMemorySize,
                       (int)node_smem);

  zero_kernel<<<(kNC * kH + 255) / 256, 256>>>();
  prep_kernel<<<(kNC + 255) / 256, 256>>>(positions, cni, mask);
  inv_kernel<<<(kNR + 255) / 256, 256>>>(positions, edge_index);
  msg_kernel<<<(kNR + TILE - 1) / TILE, TB, msg_smem>>>(
      features, positions, edge_index, W1, b1, W2, b2, P1, pb1, P2, pb2);
  node_kernel<<<(kNC + TILE - 1) / TILE, TB, node_smem>>>(
      features, degree, U1, ub1, U2, ub2, out_feat);
  pos_kernel<<<(kNC * kP + 255) / 256, 256>>>(positions, out_pos);
}

// round 3
// speedup vs baseline: 1.5943x; 1.5943x over previous
#include <cuda_runtime.h>
#include <math.h>

typedef unsigned long long ull;

namespace {
constexpr int kB = 2, kC = 20000, kH = 64, kM = 8, kE = 200000, kP = 3;
constexpr int kNR = kB * kE;      // 400000 message rows
constexpr int kNC = kB * kC;      // 40000 node rows
constexpr int kIn1 = 2 * kH + 4;  // 132
constexpr int TILE = 128;
constexpr int TB = 512;

// msg_kernel shared layout (float offsets)
constexpr int OFF_W1 = 0;           // 132*64 = 8448
constexpr int OFF_W2 = 8448;        // 4096
constexpr int OFF_P1 = 12544;       // 4096
constexpr int OFF_P2 = 16640;       // 64
constexpr int OFF_B1 = 16704;       // 64
constexpr int OFF_B2 = 16768;       // 64
constexpr int OFF_PB1 = 16832;      // 64
constexpr int OFF_X = 16896;        // 128*132 = 16896 (aliased as Msg later)
constexpr int OFF_H = 33792;        // 128*68  = 8704
constexpr int OFF_REL = 42496;      // 128*3
constexpr int OFF_WT = 42880;       // 128
constexpr int OFF_DST = 43008;      // 128 (int)
constexpr int MSG_SMEM_FLOATS = 43136;

// node_kernel shared layout
constexpr int NOFF_U1 = 0;          // 128*64 = 8192
constexpr int NOFF_U2 = 8192;       // 4096
constexpr int NOFF_UB1 = 12288;     // 64
constexpr int NOFF_UB2 = 12352;     // 64
constexpr int NOFF_X = 12416;       // 128*132 = 16896
constexpr int NOFF_H = 29312;       // 128*68  = 8704
constexpr int NODE_SMEM_FLOATS = 38016;
}  // namespace

// Scratch (static device globals: no runtime allocation)
__device__ float g_agg[kNC * kH];
__device__ float g_posupd[kNC * kP];
__device__ float g_inv[kNR * 4];
__device__ float g_npos[kNC * kM * 3];
__device__ float g_np2[kNC * kM];
__device__ float g_cent[kNC * 3];
__device__ unsigned g_mbits[kC];

// ---- packed f32x2 helpers (sm_100+ FFMA2, PTX-only path) ----
__device__ __forceinline__ ull dup2(float v) {
  ull r;
  asm("mov.b64 %0, {%1, %1};" : "=l"(r) : "f"(v));
  return r;
}
__device__ __forceinline__ void ffma2(ull& d, ull a, ull b) {
  asm("fma.rn.f32x2 %0, %1, %2, %0;" : "+l"(d) : "l"(a), "l"(b));
}
__device__ __forceinline__ float2 unpack2(ull v) {
  float2 f;
  asm("mov.b64 {%0, %1}, %2;" : "=f"(f.x), "=f"(f.y) : "l"(v));
  return f;
}

__device__ __forceinline__ float silu_f(float v) {
  return __fdividef(v, 1.f + __expf(-v));
}

// 4-row x 4-col (2 f32x2 pairs) register tile over K, x rows in smem
// (stride XS, multiple of 4), W row-major [K,64] in smem, bias[64] in smem.
template <int K, int XS>
__device__ __forceinline__ void gemm_tile_f32x2(
    const float* __restrict__ xbase, int row0, const float* __restrict__ W,
    int cg, const float* __restrict__ bias, ull acc[4][2]) {
  const float* x0 = xbase + (row0 + 0) * XS;
  const float* x1 = xbase + (row0 + 1) * XS;
  const float* x2 = xbase + (row0 + 2) * XS;
  const float* x3 = xbase + (row0 + 3) * XS;
#pragma unroll
  for (int i = 0; i < 4; i++) {
    acc[i][0] = *(const ull*)(bias + cg * 4 + 0);
    acc[i][1] = *(const ull*)(bias + cg * 4 + 2);
  }
#pragma unroll 2
  for (int k = 0; k < K; k += 4) {
    float4 xv0 = *(const float4*)(x0 + k);
    float4 xv1 = *(const float4*)(x1 + k);
    float4 xv2 = *(const float4*)(x2 + k);
    float4 xv3 = *(const float4*)(x3 + k);
#pragma unroll
    for (int kk = 0; kk < 4; kk++) {
      ulonglong2 w = *(const ulonglong2*)(W + (k + kk) * 64 + cg * 4);
      ull d0 = dup2(((const float*)&xv0)[kk]);
      ull d1 = dup2(((const float*)&xv1)[kk]);
      ull d2 = dup2(((const float*)&xv2)[kk]);
      ull d3 = dup2(((const float*)&xv3)[kk]);
      ffma2(acc[0][0], d0, w.x);
      ffma2(acc[0][1], d0, w.y);
      ffma2(acc[1][0], d1, w.x);
      ffma2(acc[1][1], d1, w.y);
      ffma2(acc[2][0], d2, w.x);
      ffma2(acc[2][1], d2, w.y);
      ffma2(acc[3][0], d3, w.x);
      ffma2(acc[3][1], d3, w.y);
    }
  }
}

__global__ void zero_kernel() {
  int i = blockIdx.x * blockDim.x + threadIdx.x;
  if (i < kNC * kH) g_agg[i] = 0.f;
  if (i < kNC * kP) g_posupd[i] = 0.f;
}

__global__ void prep_kernel(const float* __restrict__ positions,
                            const int* __restrict__ cni,
                            const float* __restrict__ mask) {
  int i = blockIdx.x * blockDim.x + threadIdx.x;
  if (i >= kNC) return;
  int b = i / kC, c = i - b * kC;
  float sx = 0.f, sy = 0.f, sz = 0.f, cnt = 0.f;
  unsigned bits = 0;
#pragma unroll
  for (int m = 0; m < kM; m++) {
    int idx = cni[c * kM + m];
    const float* p = positions + ((size_t)b * kC + idx) * kP;
    float x = p[0], y = p[1], z = p[2];
    g_npos[((size_t)i * kM + m) * 3 + 0] = x;
    g_npos[((size_t)i * kM + m) * 3 + 1] = y;
    g_npos[((size_t)i * kM + m) * 3 + 2] = z;
    g_np2[i * kM + m] = x * x + y * y + z * z;
    float mk = mask[c * kM + m];
    if (mk > 0.f) { bits |= (1u << m); sx += x; sy += y; sz += z; cnt += 1.f; }
  }
  float den = fmaxf(cnt, 1e-12f);
  g_cent[i * 3 + 0] = sx / den;
  g_cent[i * 3 + 1] = sy / den;
  g_cent[i * 3 + 2] = sz / den;
  if (b == 0) g_mbits[c] = bits;
}

__global__ void __launch_bounds__(256) inv_kernel(
    const float* __restrict__ positions, const int* __restrict__ ei) {
  int g = blockIdx.x * blockDim.x + threadIdx.x;
  if (g >= kNR) return;
  int b = g / kE, e = g - b * kE;
  int src = ei[e], dst = ei[kE + e];
  int is = b * kC + src, id = b * kC + dst;

  float sp[24], dp[24], sp2[8], dp2[8];
  {
    const float4* a = (const float4*)(g_npos + (size_t)is * 24);
    float4* o = (float4*)sp;
#pragma unroll
    for (int q = 0; q < 6; q++) o[q] = a[q];
    const float4* a2 = (const float4*)(g_npos + (size_t)id * 24);
    float4* o2 = (float4*)dp;
#pragma unroll
    for (int q = 0; q < 6; q++) o2[q] = a2[q];
    const float4* s2 = (const float4*)(g_np2 + (size_t)is * 8);
    ((float4*)sp2)[0] = s2[0]; ((float4*)sp2)[1] = s2[1];
    const float4* d2 = (const float4*)(g_np2 + (size_t)id * 8);
    ((float4*)dp2)[0] = d2[0]; ((float4*)dp2)[1] = d2[1];
  }
  unsigned mx = g_mbits[src], my = g_mbits[dst];
  float pairwise = 0.f, hxy = 0.f;
  float colmin[8];
#pragma unroll
  for (int n = 0; n < 8; n++) colmin[n] = 3.4e38f;
#pragma unroll
  for (int m = 0; m < 8; m++) {
    if ((mx >> m) & 1) {
      float rowmin = 3.4e38f;
      float ax = sp[m * 3], ay = sp[m * 3 + 1], az = sp[m * 3 + 2], a2 = sp2[m];
#pragma unroll
      for (int n = 0; n < 8; n++) {
        if ((my >> n) & 1) {
          float s = a2 + dp2[n] -
                    2.f * (ax * dp[n * 3] + ay * dp[n * 3 + 1] + az * dp[n * 3 + 2]);
          float d = sqrtf(fmaxf(s, 0.f) + 1e-12f);
          pairwise += d;
          rowmin = fminf(rowmin, d);
          colmin[n] = fminf(colmin[n], d);
        }
      }
      hxy = fmaxf(hxy, rowmin);
    }
  }
  float hyx = 0.f;
#pragma unroll
  for (int n = 0; n < 8; n++)
    if ((my >> n) & 1) hyx = fmaxf(hyx, colmin[n]);
  float haus = fmaxf(hxy, hyx);

  float c0 = g_cent[is * 3 + 0] - g_cent[id * 3 + 0];
  float c1 = g_cent[is * 3 + 1] - g_cent[id * 3 + 1];
  float c2 = g_cent[is * 3 + 2] - g_cent[id * 3 + 2];
  float centroid = sqrtf(c0 * c0 + c1 * c1 + c2 * c2);

  const float* ps = positions + (size_t)is * kP;
  const float* pd = positions + (size_t)id * kP;
  float r0 = ps[0] - pd[0], r1 = ps[1] - pd[1], r2 = ps[2] - pd[2];
  float dist = sqrtf(r0 * r0 + r1 * r1 + r2 * r2);

  ((float4*)g_inv)[g] = make_float4(dist, pairwise, centroid, haus);
}

__global__ void __launch_bounds__(TB) msg_kernel(
    const float* __restrict__ features, const float* __restrict__ positions,
    const int* __restrict__ ei,
    const float* __restrict__ W1, const float* __restrict__ b1,
    const float* __restrict__ W2, const float* __restrict__ b2,
    const float* __restrict__ P1, const float* __restrict__ pb1,
    const float* __restrict__ P2, const float* __restrict__ pb2) {
  extern __shared__ float sm[];
  float* sW1 = sm + OFF_W1;
  float* sW2 = sm + OFF_W2;
  float* sP1 = sm + OFF_P1;
  float* sP2 = sm + OFF_P2;
  float* sb1 = sm + OFF_B1;
  float* sb2 = sm + OFF_B2;
  float* spb1 = sm + OFF_PB1;
  float* sX = sm + OFF_X;   // [128][132]; cols 0..63 aliased as Msg after GEMM2
  float* sH = sm + OFF_H;   // [128][68]
  float* sRel = sm + OFF_REL;
  float* sWt = sm + OFF_WT;
  int* sDst = (int*)(sm + OFF_DST);

  int tid = threadIdx.x;
  for (int i = tid; i < kIn1 * 64; i += TB) sW1[i] = W1[i];
  for (int i = tid; i < 64 * 64; i += TB) { sW2[i] = W2[i]; sP1[i] = P1[i]; }
  if (tid < 64) { sP2[tid] = P2[tid]; sb1[tid] = b1[tid]; sb2[tid] = b2[tid]; spb1[tid] = pb1[tid]; }
  float pb2v = pb2[0];

  // ---- gather: 4 threads per row ----
  int lr = tid >> 2, ts = tid & 3;
  int gr = blockIdx.x * TILE + lr;
  if (gr < kNR) {
    int b = gr / kE, e = gr - b * kE;
    int src = ei[e], dst = ei[kE + e];
    int is = b * kC + src, id = b * kC + dst;
    const float4* fs = (const float4*)(features + (size_t)is * kH);
    const float4* fd = (const float4*)(features + (size_t)id * kH);
    float4* xr = (float4*)(sX + lr * 132);
#pragma unroll
    for (int q = 0; q < 4; q++) xr[ts * 4 + q] = fs[ts * 4 + q];
#pragma unroll
    for (int q = 0; q < 4; q++) xr[16 + ts * 4 + q] = fd[ts * 4 + q];
    if (ts == 0) {
      float4 iv = ((const float4*)g_inv)[gr];
      sX[lr * 132 + 128] = iv.x;
      sX[lr * 132 + 129] = iv.y;
      sX[lr * 132 + 130] = iv.z;
      sX[lr * 132 + 131] = iv.w;
      sDst[lr] = id;
      const float* ps = positions + (size_t)is * kP;
      const float* pd = positions + (size_t)id * kP;
      sRel[lr * 3 + 0] = ps[0] - pd[0];
      sRel[lr * 3 + 1] = ps[1] - pd[1];
      sRel[lr * 3 + 2] = ps[2] - pd[2];
    }
  } else if (ts == 0) {
    sDst[lr] = -1;
  }
  __syncthreads();

  int rg = tid >> 4, cg = tid & 15;  // rg 0..31 (4 rows each), cg 0..15 (4 cols)
  int row0 = rg * 4;
  ull acc[4][2];

  // ---- GEMM1: silu(X[128,132] @ W1 + b1) -> sH ----
  gemm_tile_f32x2<kIn1, 132>(sX, row0, sW1, cg, sb1, acc);
#pragma unroll
  for (int i = 0; i < 4; i++)
#pragma unroll
    for (int p = 0; p < 2; p++) {
      float2 h = unpack2(acc[i][p]);
      h.x = silu_f(h.x);
      h.y = silu_f(h.y);
      *(float2*)(sH + (row0 + i) * 68 + cg * 4 + 2 * p) = h;
    }
  __syncthreads();

  // ---- GEMM2: H @ W2 + b2 -> Msg (into sX cols 0..63; sX free now) ----
  gemm_tile_f32x2<64, 68>(sH, row0, sW2, cg, sb2, acc);
#pragma unroll
  for (int i = 0; i < 4; i++)
#pragma unroll
    for (int p = 0; p < 2; p++) {
      float2 v = unpack2(acc[i][p]);
      *(float2*)(sX + (row0 + i) * 132 + cg * 4 + 2 * p) = v;
    }
  __syncthreads();

  // ---- GEMM3: silu(Msg @ P1 + pb1) . P2, tanh -> wt ----
  gemm_tile_f32x2<64, 132>(sX, row0, sP1, cg, spb1, acc);
  float part[4] = {0.f, 0.f, 0.f, 0.f};
#pragma unroll
  for (int i = 0; i < 4; i++)
#pragma unroll
    for (int p = 0; p < 2; p++) {
      float2 h = unpack2(acc[i][p]);
      part[i] = fmaf(silu_f(h.x), sP2[cg * 4 + 2 * p], part[i]);
      part[i] = fmaf(silu_f(h.y), sP2[cg * 4 + 2 * p + 1], part[i]);
    }
#pragma unroll
  for (int i = 0; i < 4; i++) {
    float v = part[i];
    v += __shfl_xor_sync(0xffffffffu, v, 1);
    v += __shfl_xor_sync(0xffffffffu, v, 2);
    v += __shfl_xor_sync(0xffffffffu, v, 4);
    v += __shfl_xor_sync(0xffffffffu, v, 8);
    if (cg == 0) sWt[row0 + i] = tanhf(v + pb2v);
  }
  __syncthreads();

  // ---- scatter: messages -> agg, wt*rel -> pos_upd ----
  int ob = sDst[lr];
  if (ob >= 0) {
    float* ap = g_agg + (size_t)ob * kH;
    const float* mp = sX + lr * 132;
#pragma unroll
    for (int q = 0; q < 16; q++) atomicAdd(ap + ts * 16 + q, mp[ts * 16 + q]);
    if (ts == 0) {
      float w = sWt[lr];
      float* pp = g_posupd + (size_t)ob * kP;
      atomicAdd(pp + 0, w * sRel[lr * 3 + 0]);
      atomicAdd(pp + 1, w * sRel[lr * 3 + 1]);
      atomicAdd(pp + 2, w * sRel[lr * 3 + 2]);
    }
  }
}

__global__ void __launch_bounds__(TB) node_kernel(
    const float* __restrict__ features, const float* __restrict__ degree,
    const float* __restrict__ U1, const float* __restrict__ ub1,
    const float* __restrict__ U2, const float* __restrict__ ub2,
    float* __restrict__ out_feat) {
  extern __shared__ float sm[];
  float* sU1 = sm + NOFF_U1;
  float* sU2 = sm + NOFF_U2;
  float* sub1 = sm + NOFF_UB1;
  float* sub2 = sm + NOFF_UB2;
  float* sX = sm + NOFF_X;  // [128][132] (128 cols used)
  float* sH = sm + NOFF_H;  // [128][68]

  int tid = threadIdx.x;
  for (int i = tid; i < 128 * 64; i += TB) sU1[i] = U1[i];
  for (int i = tid; i < 64 * 64; i += TB) sU2[i] = U2[i];
  if (tid < 64) { sub1[tid] = ub1[tid]; sub2[tid] = ub2[tid]; }

  int lr = tid >> 2, ts = tid & 3;
  int gr = blockIdx.x * TILE + lr;
  if (gr < kNC) {
    int c = gr % kC;
    float invd = 1.f / fmaxf(degree[c], 1.f);
    const float4* fp = (const float4*)(features + (size_t)gr * kH);
    const float4* ap = (const float4*)(g_agg + (size_t)gr * kH);
    float4* xr = (float4*)(sX + lr * 132);
#pragma unroll
    for (int q = 0; q < 4; q++) xr[ts * 4 + q] = fp[ts * 4 + q];
#pragma unroll
    for (int q = 0; q < 4; q++) {
      float4 a = ap[ts * 4 + q];
      a.x *= invd; a.y *= invd; a.z *= invd; a.w *= invd;
      xr[16 + ts * 4 + q] = a;
    }
  }
  __syncthreads();

  int rg = tid >> 4, cg = tid & 15;
  int row0 = rg * 4;
  ull acc[4][2];

  gemm_tile_f32x2<128, 132>(sX, row0, sU1, cg, sub1, acc);
#pragma unroll
  for (int i = 0; i < 4; i++)
#pragma unroll
    for (int p = 0; p < 2; p++) {
      float2 h = unpack2(acc[i][p]);
      h.x = silu_f(h.x);
      h.y = silu_f(h.y);
      *(float2*)(sH + (row0 + i) * 68 + cg * 4 + 2 * p) = h;
    }
  __syncthreads();

  gemm_tile_f32x2<64, 68>(sH, row0, sU2, cg, sub2, acc);
#pragma unroll
  for (int i = 0; i < 4; i++) {
    int r = row0 + i;
    int g2 = blockIdx.x * TILE + r;
    if (g2 < kNC) {
      float2 v0 = unpack2(acc[i][0]);
      float2 v1 = unpack2(acc[i][1]);
      float4 o;
      o.x = sX[r * 132 + cg * 4 + 0] + v0.x;
      o.y = sX[r * 132 + cg * 4 + 1] + v0.y;
      o.z = sX[r * 132 + cg * 4 + 2] + v1.x;
      o.w = sX[r * 132 + cg * 4 + 3] + v1.y;
      ((float4*)(out_feat + (size_t)g2 * kH))[cg] = o;
    }
  }
}

__global__ void pos_kernel(const float* __restrict__ positions,
                           float* __restrict__ out_pos) {
  int i = blockIdx.x * blockDim.x + threadIdx.x;
  if (i < kNC * kP) out_pos[i] = positions[i] + g_posupd[i];
}

extern "C" void kernel_launch(void* const* d_in, const int* in_sizes, int n_in,
                              void* d_out, int out_size) {
  const float* features = (const float*)d_in[0];
  const float* positions = (const float*)d_in[1];
  const int* edge_index = (const int*)d_in[2];
  const float* degree = (const float*)d_in[3];
  const int* cni = (const int*)d_in[4];
  const float* mask = (const float*)d_in[5];
  const float* W1 = (const float*)d_in[6];
  const float* b1 = (const float*)d_in[7];
  const float* W2 = (const float*)d_in[8];
  const float* b2 = (const float*)d_in[9];
  const float* P1 = (const float*)d_in[10];
  const float* pb1 = (const float*)d_in[11];
  const float* P2 = (const float*)d_in[12];
  const float* pb2 = (const float*)d_in[13];
  const float* U1 = (const float*)d_in[14];
  const float* ub1 = (const float*)d_in[15];
  const float* U2 = (const float*)d_in[16];
  const float* ub2 = (const float*)d_in[17];

  float* out_feat = (float*)d_out;
  float* out_pos = out_feat + (size_t)kNC * kH;

  size_t msg_smem = (size_t)MSG_SMEM_FLOATS * sizeof(float);    // 172,544 B
  size_t node_smem = (size_t)NODE_SMEM_FLOATS * sizeof(float);  // 152,064 B
  cudaFuncSetAttribute(msg_kernel, cudaFuncAttributeMaxDynamicSharedMemorySize,
                       (int)msg_smem);
  cudaFuncSetAttribute(node_kernel, cudaFuncAttributeMaxDynamicSharedMemorySize,
                       (int)node_smem);

  zero_kernel<<<(kNC * kH + 255) / 256, 256>>>();
  prep_kernel<<<(kNC + 255) / 256, 256>>>(positions, cni, mask);
  inv_kernel<<<(kNR + 255) / 256, 256>>>(positions, edge_index);
  msg_kernel<<<(kNR + TILE - 1) / TILE, TB, msg_smem>>>(
      features, positions, edge_index, W1, b1, W2, b2, P1, pb1, P2, pb2);
  node_kernel<<<(kNC + TILE - 1) / TILE, TB, node_smem>>>(
      features, degree, U1, ub1, U2, ub2, out_feat);
  pos_kernel<<<(kNC * kP + 255) / 256, 256>>>(positions, out_pos);
}

// round 4
// speedup vs baseline: 2.0513x; 1.2867x over previous
#include <cuda_runtime.h>
#include <math.h>

typedef unsigned long long ull;

namespace {
constexpr int kB = 2, kC = 20000, kH = 64, kM = 8, kE = 200000, kP = 3;
constexpr int kNR = kB * kE;      // 400000 message rows (3125 * 128 exactly)
constexpr int kNC = kB * kC;      // 40000 node rows
constexpr int kIn1 = 2 * kH + 4;  // 132
constexpr int TILE = 128;
constexpr int TB = 512;

// msg_kernel shared layout (float offsets)
constexpr int OFF_W1 = 0;        // 132*64 = 8448
constexpr int OFF_W2 = 8448;     // 4096
constexpr int OFF_P1 = 12544;    // 4096
constexpr int OFF_P2 = 16640;    // 64
constexpr int OFF_B1 = 16704;    // 64
constexpr int OFF_B2 = 16768;    // 64
constexpr int OFF_PB1 = 16832;   // 64
constexpr int OFF_HM = 16896;    // 128*68 = 8704 (H, then reused as Msg)
constexpr int OFF_INV = 25600;   // 128*4
constexpr int OFF_REL = 26112;   // 128*3
constexpr int OFF_WT = 26496;    // 128
constexpr int OFF_DST = 26624;   // 128 (int)
constexpr int OFF_FS = 26752;    // 128 (int, feature elem offsets src)
constexpr int OFF_FD = 26880;    // 128 (int, feature elem offsets dst)
constexpr int MSG_SMEM_FLOATS = 27008;  // 108,032 B -> 2 blocks/SM

// node_kernel shared layout
constexpr int NOFF_U1 = 0;       // 8192
constexpr int NOFF_U2 = 8192;    // 4096
constexpr int NOFF_UB1 = 12288;  // 64
constexpr int NOFF_UB2 = 12352;  // 64
constexpr int NOFF_HM = 12416;   // 8704
constexpr int NOFF_IDG = 21120;  // 128 (invd per row)
constexpr int NODE_SMEM_FLOATS = 21248;  // 84,992 B -> 2 blocks/SM
}  // namespace

// Scratch (static device globals: no runtime allocation)
__device__ float g_agg[kNC * kH];
__device__ float g_posupd[kNC * kP];
__device__ float g_inv[kNR * 4];
__device__ float g_npos[kNC * kM * 3];
__device__ float g_np2[kNC * kM];
__device__ float g_cent[kNC * 3];
__device__ unsigned g_mbits[kC];

// ---- packed f32x2 helpers (sm_100+ FFMA2, PTX-only path) ----
__device__ __forceinline__ ull dup2(float v) {
  ull r;
  asm("mov.b64 %0, {%1, %1};" : "=l"(r) : "f"(v));
  return r;
}
__device__ __forceinline__ void ffma2(ull& d, ull a, ull b) {
  asm("fma.rn.f32x2 %0, %1, %2, %0;" : "+l"(d) : "l"(a), "l"(b));
}
// d = d * a + b  (packed)
__device__ __forceinline__ void fma2_scale_bias(ull& d, ull a, ull b) {
  asm("fma.rn.f32x2 %0, %0, %1, %2;" : "+l"(d) : "l"(a), "l"(b));
}
__device__ __forceinline__ float2 unpack2(ull v) {
  float2 f;
  asm("mov.b64 {%0, %1}, %2;" : "=f"(f.x), "=f"(f.y) : "l"(v));
  return f;
}
__device__ __forceinline__ void red_add_v4(float* p, float a, float b, float c,
                                           float d) {
  asm volatile("red.global.add.v4.f32 [%0], {%1, %2, %3, %4};" ::"l"(p), "f"(a),
               "f"(b), "f"(c), "f"(d)
               : "memory");
}

__device__ __forceinline__ float silu_f(float v) {
  return __fdividef(v, 1.f + __expf(-v));
}

// 64-k-step (16 groups of 4) GEMM fragment: 4 rows (x0..x3, contiguous in k)
// times W[64 rows x 64 cols row-major], accumulating into acc (4 rows x 4 cols
// as 2 f32x2 pairs). cg in [0,16).
__device__ __forceinline__ void gemm16(const float* __restrict__ x0,
                                       const float* __restrict__ x1,
                                       const float* __restrict__ x2,
                                       const float* __restrict__ x3,
                                       const float* __restrict__ W, int cg,
                                       ull acc[4][2]) {
#pragma unroll 2
  for (int g = 0; g < 16; g++) {
    float4 xv0 = *(const float4*)(x0 + 4 * g);
    float4 xv1 = *(const float4*)(x1 + 4 * g);
    float4 xv2 = *(const float4*)(x2 + 4 * g);
    float4 xv3 = *(const float4*)(x3 + 4 * g);
#pragma unroll
    for (int kk = 0; kk < 4; kk++) {
      ulonglong2 w = *(const ulonglong2*)(W + (4 * g + kk) * 64 + cg * 4);
      ull d0 = dup2(((const float*)&xv0)[kk]);
      ull d1 = dup2(((const float*)&xv1)[kk]);
      ull d2 = dup2(((const float*)&xv2)[kk]);
      ull d3 = dup2(((const float*)&xv3)[kk]);
      ffma2(acc[0][0], d0, w.x);
      ffma2(acc[0][1], d0, w.y);
      ffma2(acc[1][0], d1, w.x);
      ffma2(acc[1][1], d1, w.y);
      ffma2(acc[2][0], d2, w.x);
      ffma2(acc[2][1], d2, w.y);
      ffma2(acc[3][0], d3, w.x);
      ffma2(acc[3][1], d3, w.y);
    }
  }
}

__global__ void zero_kernel() {
  int i = blockIdx.x * blockDim.x + threadIdx.x;
  if (i < kNC * kH) g_agg[i] = 0.f;
  if (i < kNC * kP) g_posupd[i] = 0.f;
}

__global__ void prep_kernel(const float* __restrict__ positions,
                            const int* __restrict__ cni,
                            const float* __restrict__ mask) {
  int i = blockIdx.x * blockDim.x + threadIdx.x;
  if (i >= kNC) return;
  int b = i / kC, c = i - b * kC;
  float sx = 0.f, sy = 0.f, sz = 0.f, cnt = 0.f;
  unsigned bits = 0;
#pragma unroll
  for (int m = 0; m < kM; m++) {
    int idx = cni[c * kM + m];
    const float* p = positions + ((size_t)b * kC + idx) * kP;
    float x = p[0], y = p[1], z = p[2];
    g_npos[((size_t)i * kM + m) * 3 + 0] = x;
    g_npos[((size_t)i * kM + m) * 3 + 1] = y;
    g_npos[((size_t)i * kM + m) * 3 + 2] = z;
    g_np2[i * kM + m] = x * x + y * y + z * z;
    float mk = mask[c * kM + m];
    if (mk > 0.f) { bits |= (1u << m); sx += x; sy += y; sz += z; cnt += 1.f; }
  }
  float den = fmaxf(cnt, 1e-12f);
  g_cent[i * 3 + 0] = sx / den;
  g_cent[i * 3 + 1] = sy / den;
  g_cent[i * 3 + 2] = sz / den;
  if (b == 0) g_mbits[c] = bits;
}

__global__ void __launch_bounds__(256) inv_kernel(
    const float* __restrict__ positions, const int* __restrict__ ei) {
  int g = blockIdx.x * blockDim.x + threadIdx.x;
  if (g >= kNR) return;
  int b = g / kE, e = g - b * kE;
  int src = ei[e], dst = ei[kE + e];
  int is = b * kC + src, id = b * kC + dst;

  float sp[24], dp[24], sp2[8], dp2[8];
  {
    const float4* a = (const float4*)(g_npos + (size_t)is * 24);
    float4* o = (float4*)sp;
#pragma unroll
    for (int q = 0; q < 6; q++) o[q] = a[q];
    const float4* a2 = (const float4*)(g_npos + (size_t)id * 24);
    float4* o2 = (float4*)dp;
#pragma unroll
    for (int q = 0; q < 6; q++) o2[q] = a2[q];
    const float4* s2 = (const float4*)(g_np2 + (size_t)is * 8);
    ((float4*)sp2)[0] = s2[0]; ((float4*)sp2)[1] = s2[1];
    const float4* d2 = (const float4*)(g_np2 + (size_t)id * 8);
    ((float4*)dp2)[0] = d2[0]; ((float4*)dp2)[1] = d2[1];
  }
  unsigned mx = g_mbits[src], my = g_mbits[dst];
  float pairwise = 0.f, hxy = 0.f;
  float colmin[8];
#pragma unroll
  for (int n = 0; n < 8; n++) colmin[n] = 3.4e38f;
#pragma unroll
  for (int m = 0; m < 8; m++) {
    if ((mx >> m) & 1) {
      float rowmin = 3.4e38f;
      float ax = sp[m * 3], ay = sp[m * 3 + 1], az = sp[m * 3 + 2], a2 = sp2[m];
#pragma unroll
      for (int n = 0; n < 8; n++) {
        if ((my >> n) & 1) {
          float s = a2 + dp2[n] -
                    2.f * (ax * dp[n * 3] + ay * dp[n * 3 + 1] + az * dp[n * 3 + 2]);
          float d = sqrtf(fmaxf(s, 0.f) + 1e-12f);
          pairwise += d;
          rowmin = fminf(rowmin, d);
          colmin[n] = fminf(colmin[n], d);
        }
      }
      hxy = fmaxf(hxy, rowmin);
    }
  }
  float hyx = 0.f;
#pragma unroll
  for (int n = 0; n < 8; n++)
    if ((my >> n) & 1) hyx = fmaxf(hyx, colmin[n]);
  float haus = fmaxf(hxy, hyx);

  float c0 = g_cent[is * 3 + 0] - g_cent[id * 3 + 0];
  float c1 = g_cent[is * 3 + 1] - g_cent[id * 3 + 1];
  float c2 = g_cent[is * 3 + 2] - g_cent[id * 3 + 2];
  float centroid = sqrtf(c0 * c0 + c1 * c1 + c2 * c2);

  const float* ps = positions + (size_t)is * kP;
  const float* pd = positions + (size_t)id * kP;
  float r0 = ps[0] - pd[0], r1 = ps[1] - pd[1], r2 = ps[2] - pd[2];
  float dist = sqrtf(r0 * r0 + r1 * r1 + r2 * r2);

  ((float4*)g_inv)[g] = make_float4(dist, pairwise, centroid, haus);
}

__global__ void __launch_bounds__(TB, 2) msg_kernel(
    const float* __restrict__ features, const float* __restrict__ positions,
    const int* __restrict__ ei,
    const float* __restrict__ W1, const float* __restrict__ b1,
    const float* __restrict__ W2, const float* __restrict__ b2,
    const float* __restrict__ P1, const float* __restrict__ pb1,
    const float* __restrict__ P2, const float* __restrict__ pb2) {
  extern __shared__ float sm[];
  float* sW1 = sm + OFF_W1;
  float* sW2 = sm + OFF_W2;
  float* sP1 = sm + OFF_P1;
  float* sP2 = sm + OFF_P2;
  float* sb1 = sm + OFF_B1;
  float* sb2 = sm + OFF_B2;
  float* spb1 = sm + OFF_PB1;
  float* sHM = sm + OFF_HM;   // [128][68] H, then Msg
  float* sInv = sm + OFF_INV; // [128][4]
  float* sRel = sm + OFF_REL;
  float* sWt = sm + OFF_WT;
  int* sDst = (int*)(sm + OFF_DST);
  int* sFs = (int*)(sm + OFF_FS);
  int* sFd = (int*)(sm + OFF_FD);

  int tid = threadIdx.x;
  for (int i = tid; i < kIn1 * 64; i += TB) sW1[i] = W1[i];
  for (int i = tid; i < 64 * 64; i += TB) { sW2[i] = W2[i]; sP1[i] = P1[i]; }
  if (tid < 64) { sP2[tid] = P2[tid]; sb1[tid] = b1[tid]; sb2[tid] = b2[tid]; spb1[tid] = pb1[tid]; }
  float pb2v = pb2[0];

  // ---- gather (indices + invariants only; features stay in L1/L2) ----
  if (tid < TILE) {
    int gr = blockIdx.x * TILE + tid;  // grid covers kNR exactly
    int b = gr / kE, e = gr - b * kE;
    int src = ei[e], dst = ei[kE + e];
    int is = b * kC + src, id = b * kC + dst;
    sFs[tid] = is * kH;
    sFd[tid] = id * kH;
    sDst[tid] = id;
    ((float4*)sInv)[tid] = ((const float4*)g_inv)[gr];
    const float* ps = positions + (size_t)is * kP;
    const float* pd = positions + (size_t)id * kP;
    sRel[tid * 3 + 0] = ps[0] - pd[0];
    sRel[tid * 3 + 1] = ps[1] - pd[1];
    sRel[tid * 3 + 2] = ps[2] - pd[2];
  }
  __syncthreads();

  int rg = tid >> 4, cg = tid & 15;  // rg 0..31 (4 rows each), cg 0..15
  int row0 = rg * 4;
  ull acc[4][2];
#pragma unroll
  for (int i = 0; i < 4; i++) {
    acc[i][0] = *(const ull*)(sb1 + cg * 4 + 0);
    acc[i][1] = *(const ull*)(sb1 + cg * 4 + 2);
  }

  // ---- GEMM1: silu([h_src|h_dst|inv] @ W1 + b1) -> sHM ----
  {
    const float* f0 = features + sFs[row0 + 0];
    const float* f1 = features + sFs[row0 + 1];
    const float* f2 = features + sFs[row0 + 2];
    const float* f3 = features + sFs[row0 + 3];
    gemm16(f0, f1, f2, f3, sW1, cg, acc);
    const float* g0 = features + sFd[row0 + 0];
    const float* g1 = features + sFd[row0 + 1];
    const float* g2 = features + sFd[row0 + 2];
    const float* g3 = features + sFd[row0 + 3];
    gemm16(g0, g1, g2, g3, sW1 + 64 * 64, cg, acc);
    float4 iv0 = ((const float4*)sInv)[row0 + 0];
    float4 iv1 = ((const float4*)sInv)[row0 + 1];
    float4 iv2 = ((const float4*)sInv)[row0 + 2];
    float4 iv3 = ((const float4*)sInv)[row0 + 3];
#pragma unroll
    for (int kk = 0; kk < 4; kk++) {
      ulonglong2 w = *(const ulonglong2*)(sW1 + (128 + kk) * 64 + cg * 4);
      ull d0 = dup2(((const float*)&iv0)[kk]);
      ull d1 = dup2(((const float*)&iv1)[kk]);
      ull d2 = dup2(((const float*)&iv2)[kk]);
      ull d3 = dup2(((const float*)&iv3)[kk]);
      ffma2(acc[0][0], d0, w.x);
      ffma2(acc[0][1], d0, w.y);
      ffma2(acc[1][0], d1, w.x);
      ffma2(acc[1][1], d1, w.y);
      ffma2(acc[2][0], d2, w.x);
      ffma2(acc[2][1], d2, w.y);
      ffma2(acc[3][0], d3, w.x);
      ffma2(acc[3][1], d3, w.y);
    }
  }
#pragma unroll
  for (int i = 0; i < 4; i++)
#pragma unroll
    for (int p = 0; p < 2; p++) {
      float2 h = unpack2(acc[i][p]);
      h.x = silu_f(h.x);
      h.y = silu_f(h.y);
      *(float2*)(sHM + (row0 + i) * 68 + cg * 4 + 2 * p) = h;
    }
  __syncthreads();

  // ---- GEMM2: Msg = H @ W2 + b2 (into regs) ----
#pragma unroll
  for (int i = 0; i < 4; i++) {
    acc[i][0] = *(const ull*)(sb2 + cg * 4 + 0);
    acc[i][1] = *(const ull*)(sb2 + cg * 4 + 2);
  }
  gemm16(sHM + (row0 + 0) * 68, sHM + (row0 + 1) * 68, sHM + (row0 + 2) * 68,
         sHM + (row0 + 3) * 68, sW2, cg, acc);
  __syncthreads();  // all H reads done; safe to overwrite buffer with Msg
#pragma unroll
  for (int i = 0; i < 4; i++)
#pragma unroll
    for (int p = 0; p < 2; p++) {
      float2 v = unpack2(acc[i][p]);
      *(float2*)(sHM + (row0 + i) * 68 + cg * 4 + 2 * p) = v;
    }
  __syncthreads();

  // ---- GEMM3: silu(Msg @ P1 + pb1) . P2, tanh -> wt ----
#pragma unroll
  for (int i = 0; i < 4; i++) {
    acc[i][0] = *(const ull*)(spb1 + cg * 4 + 0);
    acc[i][1] = *(const ull*)(spb1 + cg * 4 + 2);
  }
  gemm16(sHM + (row0 + 0) * 68, sHM + (row0 + 1) * 68, sHM + (row0 + 2) * 68,
         sHM + (row0 + 3) * 68, sP1, cg, acc);
  float part[4] = {0.f, 0.f, 0.f, 0.f};
#pragma unroll
  for (int i = 0; i < 4; i++)
#pragma unroll
    for (int p = 0; p < 2; p++) {
      float2 h = unpack2(acc[i][p]);
      part[i] = fmaf(silu_f(h.x), sP2[cg * 4 + 2 * p], part[i]);
      part[i] = fmaf(silu_f(h.y), sP2[cg * 4 + 2 * p + 1], part[i]);
    }
#pragma unroll
  for (int i = 0; i < 4; i++) {
    float v = part[i];
    v += __shfl_xor_sync(0xffffffffu, v, 1);
    v += __shfl_xor_sync(0xffffffffu, v, 2);
    v += __shfl_xor_sync(0xffffffffu, v, 4);
    v += __shfl_xor_sync(0xffffffffu, v, 8);
    if (cg == 0) sWt[row0 + i] = tanhf(v + pb2v);
  }
  __syncthreads();

  // ---- scatter: messages -> agg (vector red), wt*rel -> pos_upd ----
  int lr = tid >> 2, ts = tid & 3;
  int ob = sDst[lr];
  float* ap = g_agg + (size_t)ob * kH + ts * 16;
  const float* mp = sHM + lr * 68 + ts * 16;
#pragma unroll
  for (int q = 0; q < 4; q++)
    red_add_v4(ap + q * 4, mp[q * 4 + 0], mp[q * 4 + 1], mp[q * 4 + 2],
               mp[q * 4 + 3]);
  if (ts == 0) {
    float w = sWt[lr];
    float* pp = g_posupd + (size_t)ob * kP;
    atomicAdd(pp + 0, w * sRel[lr * 3 + 0]);
    atomicAdd(pp + 1, w * sRel[lr * 3 + 1]);
    atomicAdd(pp + 2, w * sRel[lr * 3 + 2]);
  }
}

__global__ void __launch_bounds__(TB, 2) node_kernel(
    const float* __restrict__ features, const float* __restrict__ degree,
    const float* __restrict__ U1, const float* __restrict__ ub1,
    const float* __restrict__ U2, const float* __restrict__ ub2,
    float* __restrict__ out_feat) {
  extern __shared__ float sm[];
  float* sU1 = sm + NOFF_U1;
  float* sU2 = sm + NOFF_U2;
  float* sub1 = sm + NOFF_UB1;
  float* sub2 = sm + NOFF_UB2;
  float* sHM = sm + NOFF_HM;   // [128][68]
  float* sInvD = sm + NOFF_IDG;

  int tid = threadIdx.x;
  for (int i = tid; i < 128 * 64; i += TB) sU1[i] = U1[i];
  for (int i = tid; i < 64 * 64; i += TB) sU2[i] = U2[i];
  if (tid < 64) { sub1[tid] = ub1[tid]; sub2[tid] = ub2[tid]; }

  if (tid < TILE) {
    int gr = blockIdx.x * TILE + tid;
    int grc = gr < kNC ? gr : kNC - 1;
    int c = grc % kC;
    sInvD[tid] = 1.f / fmaxf(degree[c], 1.f);
  }
  __syncthreads();

  int rg = tid >> 4, cg = tid & 15;
  int row0 = rg * 4;
  int gr0 = blockIdx.x * TILE + row0;
  int r0c = min(gr0 + 0, kNC - 1);
  int r1c = min(gr0 + 1, kNC - 1);
  int r2c = min(gr0 + 2, kNC - 1);
  int r3c = min(gr0 + 3, kNC - 1);

  ull acc[4][2];
#pragma unroll
  for (int i = 0; i < 4; i++) { acc[i][0] = 0ull; acc[i][1] = 0ull; }

  // segment B first: agg rows (unscaled), then acc = acc*invd + bias
  gemm16(g_agg + (size_t)r0c * kH, g_agg + (size_t)r1c * kH,
         g_agg + (size_t)r2c * kH, g_agg + (size_t)r3c * kH, sU1 + 64 * 64, cg,
         acc);
  {
    ull bias0 = *(const ull*)(sub1 + cg * 4 + 0);
    ull bias1 = *(const ull*)(sub1 + cg * 4 + 2);
#pragma unroll
    for (int i = 0; i < 4; i++) {
      ull dv = dup2(sInvD[row0 + i]);
      fma2_scale_bias(acc[i][0], dv, bias0);
      fma2_scale_bias(acc[i][1], dv, bias1);
    }
  }
  gemm16(features + (size_t)r0c * kH, features + (size_t)r1c * kH,
         features + (size_t)r2c * kH, features + (size_t)r3c * kH, sU1, cg,
         acc);
#pragma unroll
  for (int i = 0; i < 4; i++)
#pragma unroll
    for (int p = 0; p < 2; p++) {
      float2 h = unpack2(acc[i][p]);
      h.x = silu_f(h.x);
      h.y = silu_f(h.y);
      *(float2*)(sHM + (row0 + i) * 68 + cg * 4 + 2 * p) = h;
    }
  __syncthreads();

#pragma unroll
  for (int i = 0; i < 4; i++) {
    acc[i][0] = *(const ull*)(sub2 + cg * 4 + 0);
    acc[i][1] = *(const ull*)(sub2 + cg * 4 + 2);
  }
  gemm16(sHM + (row0 + 0) * 68, sHM + (row0 + 1) * 68, sHM + (row0 + 2) * 68,
         sHM + (row0 + 3) * 68, sU2, cg, acc);
#pragma unroll
  for (int i = 0; i < 4; i++) {
    int g2 = gr0 + i;
    if (g2 < kNC) {
      const float4 f = ((const float4*)(features + (size_t)g2 * kH))[cg];
      float2 v0 = unpack2(acc[i][0]);
      float2 v1 = unpack2(acc[i][1]);
      float4 o;
      o.x = f.x + v0.x;
      o.y = f.y + v0.y;
      o.z = f.z + v1.x;
      o.w = f.w + v1.y;
      ((float4*)(out_feat + (size_t)g2 * kH))[cg] = o;
    }
  }
}

__global__ void pos_kernel(const float* __restrict__ positions,
                           float* __restrict__ out_pos) {
  int i = blockIdx.x * blockDim.x + threadIdx.x;
  if (i < kNC * kP) out_pos[i] = positions[i] + g_posupd[i];
}

extern "C" void kernel_launch(void* const* d_in, const int* in_sizes, int n_in,
                              void* d_out, int out_size) {
  const float* features = (const float*)d_in[0];
  const float* positions = (const float*)d_in[1];
  const int* edge_index = (const int*)d_in[2];
  const float* degree = (const float*)d_in[3];
  const int* cni = (const int*)d_in[4];
  const float* mask = (const float*)d_in[5];
  const float* W1 = (const float*)d_in[6];
  const float* b1 = (const float*)d_in[7];
  const float* W2 = (const float*)d_in[8];
  const float* b2 = (const float*)d_in[9];
  const float* P1 = (const float*)d_in[10];
  const float* pb1 = (const float*)d_in[11];
  const float* P2 = (const float*)d_in[12];
  const float* pb2 = (const float*)d_in[13];
  const float* U1 = (const float*)d_in[14];
  const float* ub1 = (const float*)d_in[15];
  const float* U2 = (const float*)d_in[16];
  const float* ub2 = (const float*)d_in[17];

  float* out_feat = (float*)d_out;
  float* out_pos = out_feat + (size_t)kNC * kH;

  size_t msg_smem = (size_t)MSG_SMEM_FLOATS * sizeof(float);    // 108,032 B
  size_t node_smem = (size_t)NODE_SMEM_FLOATS * sizeof(float);  // 84,992 B
  cudaFuncSetAttribute(msg_kernel, cudaFuncAttributeMaxDynamicSharedMemorySize,
                       (int)msg_smem);
  cudaFuncSetAttribute(node_kernel, cudaFuncAttributeMaxDynamicSharedMemorySize,
                       (int)node_smem);

  zero_kernel<<<(kNC * kH + 255) / 256, 256>>>();
  prep_kernel<<<(kNC + 255) / 256, 256>>>(positions, cni, mask);
  inv_kernel<<<(kNR + 255) / 256, 256>>>(positions, edge_index);
  msg_kernel<<<kNR / TILE, TB, msg_smem>>>(features, positions, edge_index, W1,
                                           b1, W2, b2, P1, pb1, P2, pb2);
  node_kernel<<<(kNC + TILE - 1) / TILE, TB, node_smem>>>(
      features, degree, U1, ub1, U2, ub2, out_feat);
  pos_kernel<<<(kNC * kP + 255) / 256, 256>>>(positions, out_pos);
}

// round 5
// speedup vs baseline: 2.2173x; 1.0809x over previous
#include <cuda_runtime.h>
#include <math.h>

typedef unsigned long long ull;

namespace {
constexpr int kB = 2, kC = 20000, kH = 64, kM = 8, kE = 200000, kP = 3;
constexpr int kNR = kB * kE;      // 400000 message rows (3125 * 128 exactly)
constexpr int kNC = kB * kC;      // 40000 node rows
constexpr int kIn1 = 2 * kH + 4;  // 132
constexpr int TILE = 128;
constexpr int TBM = 256;          // msg block threads (8x4 reg tiles)
constexpr int TB = 512;           // node block threads

// msg_kernel shared layout (float offsets)
constexpr int OFF_W1 = 0;        // 132*64 = 8448
constexpr int OFF_W2 = 8448;     // 4096
constexpr int OFF_P1 = 12544;    // 4096
constexpr int OFF_P2 = 16640;    // 64
constexpr int OFF_B1 = 16704;    // 64
constexpr int OFF_B2 = 16768;    // 64
constexpr int OFF_PB1 = 16832;   // 64
constexpr int OFF_HM = 16896;    // 128*68 = 8704 (H, then reused as Msg)
constexpr int OFF_INV = 25600;   // 128*4
constexpr int OFF_REL = 26112;   // 128*3
constexpr int OFF_WT = 26496;    // 128
constexpr int OFF_DST = 26624;   // 128 (int)
constexpr int OFF_FS = 26752;    // 128 (int, feature elem offsets src)
constexpr int OFF_FD = 26880;    // 128 (int, feature elem offsets dst)
constexpr int MSG_SMEM_FLOATS = 27008;  // 108,032 B -> 2 blocks/SM

// node_kernel shared layout
constexpr int NOFF_U1 = 0;       // 8192
constexpr int NOFF_U2 = 8192;    // 4096
constexpr int NOFF_UB1 = 12288;  // 64
constexpr int NOFF_UB2 = 12352;  // 64
constexpr int NOFF_HM = 12416;   // 8704
constexpr int NOFF_IDG = 21120;  // 128 (invd per row)
constexpr int NODE_SMEM_FLOATS = 21248;  // 84,992 B -> 2 blocks/SM
}  // namespace

// Scratch (static device globals: no runtime allocation)
__device__ float g_agg[kNC * kH];
__device__ float g_posupd[kNC * kP];
__device__ float g_inv[kNR * 4];
__device__ float g_npos[kNC * kM * 3];
__device__ float g_np2[kNC * kM];
__device__ float g_cent[kNC * 3];
__device__ unsigned g_mbits[kC];

// ---- packed f32x2 helpers (sm_100+ FFMA2, PTX-only path) ----
__device__ __forceinline__ ull dup2(float v) {
  ull r;
  asm("mov.b64 %0, {%1, %1};" : "=l"(r) : "f"(v));
  return r;
}
__device__ __forceinline__ void ffma2(ull& d, ull a, ull b) {
  asm("fma.rn.f32x2 %0, %1, %2, %0;" : "+l"(d) : "l"(a), "l"(b));
}
// d = d * a + b  (packed)
__device__ __forceinline__ void fma2_scale_bias(ull& d, ull a, ull b) {
  asm("fma.rn.f32x2 %0, %0, %1, %2;" : "+l"(d) : "l"(a), "l"(b));
}
__device__ __forceinline__ float2 unpack2(ull v) {
  float2 f;
  asm("mov.b64 {%0, %1}, %2;" : "=f"(f.x), "=f"(f.y) : "l"(v));
  return f;
}
__device__ __forceinline__ void red_add_v4(float* p, float a, float b, float c,
                                           float d) {
  asm volatile("red.global.add.v4.f32 [%0], {%1, %2, %3, %4};" ::"l"(p), "f"(a),
               "f"(b), "f"(c), "f"(d)
               : "memory");
}

__device__ __forceinline__ float silu_f(float v) {
  return __fdividef(v, 1.f + __expf(-v));
}

// ---- 8-row x 4-col (2 f32x2 pairs) tile, 64 k-steps ----
// xp[8]: per-row pointers (k-contiguous). W row-major [64,64]. cg in [0,16).
__device__ __forceinline__ void gemm64_8(const float* const xp[8],
                                         const float* __restrict__ W, int cg,
                                         ull acc[8][2]) {
#pragma unroll
  for (int g = 0; g < 16; g++) {
    float4 xv[8];
#pragma unroll
    for (int r = 0; r < 8; r++) xv[r] = *(const float4*)(xp[r] + 4 * g);
#pragma unroll
    for (int kk = 0; kk < 4; kk++) {
      ulonglong2 w = *(const ulonglong2*)(W + (4 * g + kk) * 64 + cg * 4);
#pragma unroll
      for (int r = 0; r < 8; r++) {
        ull d = dup2(((const float*)&xv[r])[kk]);
        ffma2(acc[r][0], d, w.x);
        ffma2(acc[r][1], d, w.y);
      }
    }
  }
}

// 4-row version (node kernel, 4x4 tiles)
__device__ __forceinline__ void gemm16(const float* __restrict__ x0,
                                       const float* __restrict__ x1,
                                       const float* __restrict__ x2,
                                       const float* __restrict__ x3,
                                       const float* __restrict__ W, int cg,
                                       ull acc[4][2]) {
#pragma unroll 2
  for (int g = 0; g < 16; g++) {
    float4 xv0 = *(const float4*)(x0 + 4 * g);
    float4 xv1 = *(const float4*)(x1 + 4 * g);
    float4 xv2 = *(const float4*)(x2 + 4 * g);
    float4 xv3 = *(const float4*)(x3 + 4 * g);
#pragma unroll
    for (int kk = 0; kk < 4; kk++) {
      ulonglong2 w = *(const ulonglong2*)(W + (4 * g + kk) * 64 + cg * 4);
      ull d0 = dup2(((const float*)&xv0)[kk]);
      ull d1 = dup2(((const float*)&xv1)[kk]);
      ull d2 = dup2(((const float*)&xv2)[kk]);
      ull d3 = dup2(((const float*)&xv3)[kk]);
      ffma2(acc[0][0], d0, w.x);
      ffma2(acc[0][1], d0, w.y);
      ffma2(acc[1][0], d1, w.x);
      ffma2(acc[1][1], d1, w.y);
      ffma2(acc[2][0], d2, w.x);
      ffma2(acc[2][1], d2, w.y);
      ffma2(acc[3][0], d3, w.x);
      ffma2(acc[3][1], d3, w.y);
    }
  }
}

__global__ void zero_kernel() {
  int i = blockIdx.x * blockDim.x + threadIdx.x;
  if (i < kNC * kH) g_agg[i] = 0.f;
  if (i < kNC * kP) g_posupd[i] = 0.f;
}

__global__ void prep_kernel(const float* __restrict__ positions,
                            const int* __restrict__ cni,
                            const float* __restrict__ mask) {
  int i = blockIdx.x * blockDim.x + threadIdx.x;
  if (i >= kNC) return;
  int b = i / kC, c = i - b * kC;
  float sx = 0.f, sy = 0.f, sz = 0.f, cnt = 0.f;
  unsigned bits = 0;
#pragma unroll
  for (int m = 0; m < kM; m++) {
    int idx = cni[c * kM + m];
    const float* p = positions + ((size_t)b * kC + idx) * kP;
    float x = p[0], y = p[1], z = p[2];
    g_npos[((size_t)i * kM + m) * 3 + 0] = x;
    g_npos[((size_t)i * kM + m) * 3 + 1] = y;
    g_npos[((size_t)i * kM + m) * 3 + 2] = z;
    g_np2[i * kM + m] = x * x + y * y + z * z;
    float mk = mask[c * kM + m];
    if (mk > 0.f) { bits |= (1u << m); sx += x; sy += y; sz += z; cnt += 1.f; }
  }
  float den = fmaxf(cnt, 1e-12f);
  g_cent[i * 3 + 0] = sx / den;
  g_cent[i * 3 + 1] = sy / den;
  g_cent[i * 3 + 2] = sz / den;
  if (b == 0) g_mbits[c] = bits;
}

__global__ void __launch_bounds__(256) inv_kernel(
    const float* __restrict__ positions, const int* __restrict__ ei) {
  int g = blockIdx.x * blockDim.x + threadIdx.x;
  if (g >= kNR) return;
  int b = g / kE, e = g - b * kE;
  int src = ei[e], dst = ei[kE + e];
  int is = b * kC + src, id = b * kC + dst;

  float sp[24], dp[24], sp2[8], dp2[8];
  {
    const float4* a = (const float4*)(g_npos + (size_t)is * 24);
    float4* o = (float4*)sp;
#pragma unroll
    for (int q = 0; q < 6; q++) o[q] = a[q];
    const float4* a2 = (const float4*)(g_npos + (size_t)id * 24);
    float4* o2 = (float4*)dp;
#pragma unroll
    for (int q = 0; q < 6; q++) o2[q] = a2[q];
    const float4* s2 = (const float4*)(g_np2 + (size_t)is * 8);
    ((float4*)sp2)[0] = s2[0]; ((float4*)sp2)[1] = s2[1];
    const float4* d2 = (const float4*)(g_np2 + (size_t)id * 8);
    ((float4*)dp2)[0] = d2[0]; ((float4*)dp2)[1] = d2[1];
  }
  unsigned mx = g_mbits[src], my = g_mbits[dst];
  float pairwise = 0.f, hxy = 0.f;
  float colmin[8];
#pragma unroll
  for (int n = 0; n < 8; n++) colmin[n] = 3.4e38f;
#pragma unroll
  for (int m = 0; m < 8; m++) {
    if ((mx >> m) & 1) {
      float rowmin = 3.4e38f;
      float ax = sp[m * 3], ay = sp[m * 3 + 1], az = sp[m * 3 + 2], a2 = sp2[m];
#pragma unroll
      for (int n = 0; n < 8; n++) {
        if ((my >> n) & 1) {
          float s = a2 + dp2[n] -
                    2.f * (ax * dp[n * 3] + ay * dp[n * 3 + 1] + az * dp[n * 3 + 2]);
          float d = sqrtf(fmaxf(s, 0.f) + 1e-12f);
          pairwise += d;
          rowmin = fminf(rowmin, d);
          colmin[n] = fminf(colmin[n], d);
        }
      }
      hxy = fmaxf(hxy, rowmin);
    }
  }
  float hyx = 0.f;
#pragma unroll
  for (int n = 0; n < 8; n++)
    if ((my >> n) & 1) hyx = fmaxf(hyx, colmin[n]);
  float haus = fmaxf(hxy, hyx);

  float c0 = g_cent[is * 3 + 0] - g_cent[id * 3 + 0];
  float c1 = g_cent[is * 3 + 1] - g_cent[id * 3 + 1];
  float c2 = g_cent[is * 3 + 2] - g_cent[id * 3 + 2];
  float centroid = sqrtf(c0 * c0 + c1 * c1 + c2 * c2);

  const float* ps = positions + (size_t)is * kP;
  const float* pd = positions + (size_t)id * kP;
  float r0 = ps[0] - pd[0], r1 = ps[1] - pd[1], r2 = ps[2] - pd[2];
  float dist = sqrtf(r0 * r0 + r1 * r1 + r2 * r2);

  ((float4*)g_inv)[g] = make_float4(dist, pairwise, centroid, haus);
}

__global__ void __launch_bounds__(TBM, 2) msg_kernel(
    const float* __restrict__ features, const float* __restrict__ positions,
    const int* __restrict__ ei,
    const float* __restrict__ W1, const float* __restrict__ b1,
    const float* __restrict__ W2, const float* __restrict__ b2,
    const float* __restrict__ P1, const float* __restrict__ pb1,
    const float* __restrict__ P2, const float* __restrict__ pb2) {
  extern __shared__ float sm[];
  float* sW1 = sm + OFF_W1;
  float* sW2 = sm + OFF_W2;
  float* sP1 = sm + OFF_P1;
  float* sP2 = sm + OFF_P2;
  float* sb1 = sm + OFF_B1;
  float* sb2 = sm + OFF_B2;
  float* spb1 = sm + OFF_PB1;
  float* sHM = sm + OFF_HM;   // [128][68] H, then Msg
  float* sInv = sm + OFF_INV; // [128][4]
  float* sRel = sm + OFF_REL;
  float* sWt = sm + OFF_WT;
  int* sDst = (int*)(sm + OFF_DST);
  int* sFs = (int*)(sm + OFF_FS);
  int* sFd = (int*)(sm + OFF_FD);

  int tid = threadIdx.x;
  for (int i = tid; i < kIn1 * 64; i += TBM) sW1[i] = W1[i];
  for (int i = tid; i < 64 * 64; i += TBM) { sW2[i] = W2[i]; sP1[i] = P1[i]; }
  if (tid < 64) { sP2[tid] = P2[tid]; sb1[tid] = b1[tid]; sb2[tid] = b2[tid]; spb1[tid] = pb1[tid]; }
  float pb2v = pb2[0];

  // ---- gather (indices + invariants only; features stay in L1/L2) ----
  if (tid < TILE) {
    int gr = blockIdx.x * TILE + tid;  // grid covers kNR exactly
    int b = gr / kE, e = gr - b * kE;
    int src = ei[e], dst = ei[kE + e];
    int is = b * kC + src, id = b * kC + dst;
    sFs[tid] = is * kH;
    sFd[tid] = id * kH;
    sDst[tid] = id;
    ((float4*)sInv)[tid] = ((const float4*)g_inv)[gr];
    const float* ps = positions + (size_t)is * kP;
    const float* pd = positions + (size_t)id * kP;
    sRel[tid * 3 + 0] = ps[0] - pd[0];
    sRel[tid * 3 + 1] = ps[1] - pd[1];
    sRel[tid * 3 + 2] = ps[2] - pd[2];
  }
  __syncthreads();

  int rg = tid >> 4, cg = tid & 15;  // rg 0..15 (8 rows each), cg 0..15
  int row0 = rg * 8;
  ull acc[8][2];
#pragma unroll
  for (int i = 0; i < 8; i++) {
    acc[i][0] = *(const ull*)(sb1 + cg * 4 + 0);
    acc[i][1] = *(const ull*)(sb1 + cg * 4 + 2);
  }

  // ---- GEMM1: silu([h_src|h_dst|inv] @ W1 + b1) -> sHM ----
  {
    const float* xp[8];
#pragma unroll
    for (int r = 0; r < 8; r++) xp[r] = features + sFs[row0 + r];
    gemm64_8(xp, sW1, cg, acc);
#pragma unroll
    for (int r = 0; r < 8; r++) xp[r] = features + sFd[row0 + r];
    gemm64_8(xp, sW1 + 64 * 64, cg, acc);
    // invariant columns (k = 128..131)
    float4 iv[8];
#pragma unroll
    for (int r = 0; r < 8; r++) iv[r] = ((const float4*)sInv)[row0 + r];
#pragma unroll
    for (int kk = 0; kk < 4; kk++) {
      ulonglong2 w = *(const ulonglong2*)(sW1 + (128 + kk) * 64 + cg * 4);
#pragma unroll
      for (int r = 0; r < 8; r++) {
        ull d = dup2(((const float*)&iv[r])[kk]);
        ffma2(acc[r][0], d, w.x);
        ffma2(acc[r][1], d, w.y);
      }
    }
  }
#pragma unroll
  for (int i = 0; i < 8; i++)
#pragma unroll
    for (int p = 0; p < 2; p++) {
      float2 h = unpack2(acc[i][p]);
      h.x = silu_f(h.x);
      h.y = silu_f(h.y);
      *(float2*)(sHM + (row0 + i) * 68 + cg * 4 + 2 * p) = h;
    }
  __syncthreads();

  // ---- GEMM2: Msg = H @ W2 + b2 (into regs) ----
#pragma unroll
  for (int i = 0; i < 8; i++) {
    acc[i][0] = *(const ull*)(sb2 + cg * 4 + 0);
    acc[i][1] = *(const ull*)(sb2 + cg * 4 + 2);
  }
  {
    const float* xp[8];
#pragma unroll
    for (int r = 0; r < 8; r++) xp[r] = sHM + (row0 + r) * 68;
    gemm64_8(xp, sW2, cg, acc);
  }
  __syncthreads();  // all H reads done; safe to overwrite buffer with Msg
#pragma unroll
  for (int i = 0; i < 8; i++)
#pragma unroll
    for (int p = 0; p < 2; p++) {
      float2 v = unpack2(acc[i][p]);
      *(float2*)(sHM + (row0 + i) * 68 + cg * 4 + 2 * p) = v;
    }
  __syncthreads();

  // ---- GEMM3: silu(Msg @ P1 + pb1) . P2, tanh -> wt ----
#pragma unroll
  for (int i = 0; i < 8; i++) {
    acc[i][0] = *(const ull*)(spb1 + cg * 4 + 0);
    acc[i][1] = *(const ull*)(spb1 + cg * 4 + 2);
  }
  {
    const float* xp[8];
#pragma unroll
    for (int r = 0; r < 8; r++) xp[r] = sHM + (row0 + r) * 68;
    gemm64_8(xp, sP1, cg, acc);
  }
  float part[8];
#pragma unroll
  for (int i = 0; i < 8; i++) {
    part[i] = 0.f;
#pragma unroll
    for (int p = 0; p < 2; p++) {
      float2 h = unpack2(acc[i][p]);
      part[i] = fmaf(silu_f(h.x), sP2[cg * 4 + 2 * p], part[i]);
      part[i] = fmaf(silu_f(h.y), sP2[cg * 4 + 2 * p + 1], part[i]);
    }
  }
#pragma unroll
  for (int i = 0; i < 8; i++) {
    float v = part[i];
    v += __shfl_xor_sync(0xffffffffu, v, 1);
    v += __shfl_xor_sync(0xffffffffu, v, 2);
    v += __shfl_xor_sync(0xffffffffu, v, 4);
    v += __shfl_xor_sync(0xffffffffu, v, 8);
    if (cg == 0) sWt[row0 + i] = tanhf(v + pb2v);
  }
  __syncthreads();

  // ---- scatter: messages -> agg (vector red), wt*rel -> pos_upd ----
  int lr = tid >> 1, ts = tid & 1;  // 2 threads per row
  int ob = sDst[lr];
  float* ap = g_agg + (size_t)ob * kH + ts * 32;
  const float* mp = sHM + lr * 68 + ts * 32;
#pragma unroll
  for (int q = 0; q < 8; q++)
    red_add_v4(ap + q * 4, mp[q * 4 + 0], mp[q * 4 + 1], mp[q * 4 + 2],
               mp[q * 4 + 3]);
  if (ts == 0) {
    float w = sWt[lr];
    float* pp = g_posupd + (size_t)ob * kP;
    atomicAdd(pp + 0, w * sRel[lr * 3 + 0]);
    atomicAdd(pp + 1, w * sRel[lr * 3 + 1]);
    atomicAdd(pp + 2, w * sRel[lr * 3 + 2]);
  }
}

__global__ void __launch_bounds__(TB, 2) node_kernel(
    const float* __restrict__ features, const float* __restrict__ degree,
    const float* __restrict__ U1, const float* __restrict__ ub1,
    const float* __restrict__ U2, const float* __restrict__ ub2,
    float* __restrict__ out_feat) {
  extern __shared__ float sm[];
  float* sU1 = sm + NOFF_U1;
  float* sU2 = sm + NOFF_U2;
  float* sub1 = sm + NOFF_UB1;
  float* sub2 = sm + NOFF_UB2;
  float* sHM = sm + NOFF_HM;   // [128][68]
  float* sInvD = sm + NOFF_IDG;

  int tid = threadIdx.x;
  for (int i = tid; i < 128 * 64; i += TB) sU1[i] = U1[i];
  for (int i = tid; i < 64 * 64; i += TB) sU2[i] = U2[i];
  if (tid < 64) { sub1[tid] = ub1[tid]; sub2[tid] = ub2[tid]; }

  if (tid < TILE) {
    int gr = blockIdx.x * TILE + tid;
    int grc = gr < kNC ? gr : kNC - 1;
    int c = grc % kC;
    sInvD[tid] = 1.f / fmaxf(degree[c], 1.f);
  }
  __syncthreads();

  int rg = tid >> 4, cg = tid & 15;
  int row0 = rg * 4;
  int gr0 = blockIdx.x * TILE + row0;
  int r0c = min(gr0 + 0, kNC - 1);
  int r1c = min(gr0 + 1, kNC - 1);
  int r2c = min(gr0 + 2, kNC - 1);
  int r3c = min(gr0 + 3, kNC - 1);

  ull acc[4][2];
#pragma unroll
  for (int i = 0; i < 4; i++) { acc[i][0] = 0ull; acc[i][1] = 0ull; }

  // segment B first: agg rows (unscaled), then acc = acc*invd + bias
  gemm16(g_agg + (size_t)r0c * kH, g_agg + (size_t)r1c * kH,
         g_agg + (size_t)r2c * kH, g_agg + (size_t)r3c * kH, sU1 + 64 * 64, cg,
         acc);
  {
    ull bias0 = *(const ull*)(sub1 + cg * 4 + 0);
    ull bias1 = *(const ull*)(sub1 + cg * 4 + 2);
#pragma unroll
    for (int i = 0; i < 4; i++) {
      ull dv = dup2(sInvD[row0 + i]);
      fma2_scale_bias(acc[i][0], dv, bias0);
      fma2_scale_bias(acc[i][1], dv, bias1);
    }
  }
  gemm16(features + (size_t)r0c * kH, features + (size_t)r1c * kH,
         features + (size_t)r2c * kH, features + (size_t)r3c * kH, sU1, cg,
         acc);
#pragma unroll
  for (int i = 0; i < 4; i++)
#pragma unroll
    for (int p = 0; p < 2; p++) {
      float2 h = unpack2(acc[i][p]);
      h.x = silu_f(h.x);
      h.y = silu_f(h.y);
      *(float2*)(sHM + (row0 + i) * 68 + cg * 4 + 2 * p) = h;
    }
  __syncthreads();

#pragma unroll
  for (int i = 0; i < 4; i++) {
    acc[i][0] = *(const ull*)(sub2 + cg * 4 + 0);
    acc[i][1] = *(const ull*)(sub2 + cg * 4 + 2);
  }
  gemm16(sHM + (row0 + 0) * 68, sHM + (row0 + 1) * 68, sHM + (row0 + 2) * 68,
         sHM + (row0 + 3) * 68, sU2, cg, acc);
#pragma unroll
  for (int i = 0; i < 4; i++) {
    int g2 = gr0 + i;
    if (g2 < kNC) {
      const float4 f = ((const float4*)(features + (size_t)g2 * kH))[cg];
      float2 v0 = unpack2(acc[i][0]);
      float2 v1 = unpack2(acc[i][1]);
      float4 o;
      o.x = f.x + v0.x;
      o.y = f.y + v0.y;
      o.z = f.z + v1.x;
      o.w = f.w + v1.y;
      ((float4*)(out_feat + (size_t)g2 * kH))[cg] = o;
    }
  }
}

__global__ void pos_kernel(const float* __restrict__ positions,
                           float* __restrict__ out_pos) {
  int i = blockIdx.x * blockDim.x + threadIdx.x;
  if (i < kNC * kP) out_pos[i] = positions[i] + g_posupd[i];
}

extern "C" void kernel_launch(void* const* d_in, const int* in_sizes, int n_in,
                              void* d_out, int out_size) {
  const float* features = (const float*)d_in[0];
  const float* positions = (const float*)d_in[1];
  const int* edge_index = (const int*)d_in[2];
  const float* degree = (const float*)d_in[3];
  const int* cni = (const int*)d_in[4];
  const float* mask = (const float*)d_in[5];
  const float* W1 = (const float*)d_in[6];
  const float* b1 = (const float*)d_in[7];
  const float* W2 = (const float*)d_in[8];
  const float* b2 = (const float*)d_in[9];
  const float* P1 = (const float*)d_in[10];
  const float* pb1 = (const float*)d_in[11];
  const float* P2 = (const float*)d_in[12];
  const float* pb2 = (const float*)d_in[13];
  const float* U1 = (const float*)d_in[14];
  const float* ub1 = (const float*)d_in[15];
  const float* U2 = (const float*)d_in[16];
  const float* ub2 = (const float*)d_in[17];

  float* out_feat = (float*)d_out;
  float* out_pos = out_feat + (size_t)kNC * kH;

  size_t msg_smem = (size_t)MSG_SMEM_FLOATS * sizeof(float);    // 108,032 B
  size_t node_smem = (size_t)NODE_SMEM_FLOATS * sizeof(float);  // 84,992 B
  cudaFuncSetAttribute(msg_kernel, cudaFuncAttributeMaxDynamicSharedMemorySize,
                       (int)msg_smem);
  cudaFuncSetAttribute(node_kernel, cudaFuncAttributeMaxDynamicSharedMemorySize,
                       (int)node_smem);

  zero_kernel<<<(kNC * kH + 255) / 256, 256>>>();
  prep_kernel<<<(kNC + 255) / 256, 256>>>(positions, cni, mask);
  inv_kernel<<<(kNR + 255) / 256, 256>>>(positions, edge_index);
  msg_kernel<<<kNR / TILE, TBM, msg_smem>>>(features, positions, edge_index, W1,
                                            b1, W2, b2, P1, pb1, P2, pb2);
  node_kernel<<<(kNC + TILE - 1) / TILE, TB, node_smem>>>(
      features, degree, U1, ub1, U2, ub2, out_feat);
  pos_kernel<<<(kNC * kP + 255) / 256, 256>>>(positions, out_pos);
}